// round 1
// baseline (speedup 1.0000x reference)
#include <cuda_runtime.h>
#include <math.h>

// Fused: binarized-conv(3x3, Cin=1, Cout=32, SAME) + global-avg-pool + dense(32->10) + softmax.
// Key identity: pooling commutes with conv. p[b,co] = conv_b[co] +
//   (1/4096) * sum_{k=0..8} sign(conv_w[k,co]) * S[b,k]
// where S[b,k] are 9 shifted-window sums of the input image, each derived from
// {total, row0, row63, col0, col63 sums, 4 corners}.

#define B_TOTAL 512
#define HW 4096          // 64*64
#define NCO 32
#define NCLS 10

__global__ __launch_bounds__(256, 4)
void fused_bnn_kernel(const float* __restrict__ x,
                      const float* __restrict__ conv_w,   // [3,3,1,32] -> [k*32+co]
                      const float* __restrict__ conv_b,   // [32]
                      const float* __restrict__ dense_w,  // [32,10] -> [co*10+n]
                      const float* __restrict__ dense_b,  // [10]
                      float* __restrict__ out)            // [512,10]
{
    __shared__ float warpsum[5][8];
    __shared__ float Ssh[9];
    __shared__ float psh[NCO];
    __shared__ float lsh[NCLS];

    const int b   = blockIdx.x;
    const int tid = threadIdx.x;              // 256 threads
    const float* img = x + (size_t)b * HW;
    const float4* img4 = reinterpret_cast<const float4*>(img);

    // Each thread: 16 consecutive floats = 4x float4. Row h = tid>>2 (64 floats/row,
    // 4 threads/row), quarter m = tid&3.
    float4 v0 = img4[tid * 4 + 0];
    float4 v1 = img4[tid * 4 + 1];
    float4 v2 = img4[tid * 4 + 2];
    float4 v3 = img4[tid * 4 + 3];

    float s = (v0.x + v0.y + v0.z + v0.w)
            + (v1.x + v1.y + v1.z + v1.w)
            + (v2.x + v2.y + v2.z + v2.w)
            + (v3.x + v3.y + v3.z + v3.w);

    const int h = tid >> 2;
    const int m = tid & 3;

    float T   = s;
    float R0  = (h == 0)  ? s : 0.0f;   // row 0 sum
    float R63 = (h == 63) ? s : 0.0f;   // row 63 sum
    float C0  = (m == 0)  ? v0.x : 0.0f; // col 0 element of this row-quarter
    float C63 = (m == 3)  ? v3.w : 0.0f; // col 63 element

    // Warp reduction of the 5 accumulators
    #pragma unroll
    for (int off = 16; off > 0; off >>= 1) {
        T   += __shfl_down_sync(0xffffffffu, T,   off);
        R0  += __shfl_down_sync(0xffffffffu, R0,  off);
        R63 += __shfl_down_sync(0xffffffffu, R63, off);
        C0  += __shfl_down_sync(0xffffffffu, C0,  off);
        C63 += __shfl_down_sync(0xffffffffu, C63, off);
    }
    const int wid = tid >> 5, lane = tid & 31;
    if (lane == 0) {
        warpsum[0][wid] = T;   warpsum[1][wid] = R0;  warpsum[2][wid] = R63;
        warpsum[3][wid] = C0;  warpsum[4][wid] = C63;
    }
    __syncthreads();

    if (tid < 5) {
        float acc = 0.0f;
        #pragma unroll
        for (int i = 0; i < 8; i++) acc += warpsum[tid][i];
        warpsum[tid][0] = acc;
    }
    __syncthreads();

    if (tid == 0) {
        float t   = warpsum[0][0];
        float r0  = warpsum[1][0];
        float r63 = warpsum[2][0];
        float c0  = warpsum[3][0];
        float c63 = warpsum[4][0];
        float x00   = img[0];          // (row0,col0)
        float x0_63 = img[63];         // (row0,col63)
        float x63_0 = img[63 * 64];    // (row63,col0)
        float x63_63= img[HW - 1];     // (row63,col63)
        // k = kh*3+kw; shift dh=kh-1, dw=kw-1.
        // dh=-1 excludes row63; dh=+1 excludes row0; dw=-1 excludes col63; dw=+1 excludes col0.
        Ssh[0] = t - r63 - c63 + x63_63;  // (-1,-1)
        Ssh[1] = t - r63;                 // (-1, 0)
        Ssh[2] = t - r63 - c0  + x63_0;   // (-1,+1)
        Ssh[3] = t - c63;                 // ( 0,-1)
        Ssh[4] = t;                       // ( 0, 0)
        Ssh[5] = t - c0;                  // ( 0,+1)
        Ssh[6] = t - r0  - c63 + x0_63;   // (+1,-1)
        Ssh[7] = t - r0;                  // (+1, 0)
        Ssh[8] = t - r0  - c0  + x00;     // (+1,+1)
    }
    __syncthreads();

    // p[co] = conv_b[co] + (1/4096) * sum_k sign(conv_w[k,co]) * S[k]
    if (tid < NCO) {
        float S[9];
        #pragma unroll
        for (int k = 0; k < 9; k++) S[k] = Ssh[k];
        float acc = 0.0f;
        #pragma unroll
        for (int k = 0; k < 9; k++) {
            float w = conv_w[k * NCO + tid];
            acc += (w >= 0.0f) ? S[k] : -S[k];
        }
        psh[tid] = conv_b[tid] + acc * (1.0f / (float)HW);
    }
    __syncthreads();

    // logits and softmax
    if (tid < NCLS) {
        float l = dense_b[tid];
        #pragma unroll
        for (int co = 0; co < NCO; co++)
            l += psh[co] * dense_w[co * NCLS + tid];
        lsh[tid] = l;
    }
    __syncthreads();

    if (tid < NCLS) {
        float mx = lsh[0];
        #pragma unroll
        for (int n = 1; n < NCLS; n++) mx = fmaxf(mx, lsh[n]);
        float denom = 0.0f;
        #pragma unroll
        for (int n = 0; n < NCLS; n++) denom += expf(lsh[n] - mx);
        out[b * NCLS + tid] = expf(lsh[tid] - mx) / denom;
    }
}

extern "C" void kernel_launch(void* const* d_in, const int* in_sizes, int n_in,
                              void* d_out, int out_size) {
    const float* x       = (const float*)d_in[0];
    const float* conv_w  = (const float*)d_in[1];
    const float* conv_b  = (const float*)d_in[2];
    const float* dense_w = (const float*)d_in[3];
    const float* dense_b = (const float*)d_in[4];
    float* out = (float*)d_out;
    (void)in_sizes; (void)n_in; (void)out_size;

    fused_bnn_kernel<<<B_TOTAL, 256>>>(x, conv_w, conv_b, dense_w, dense_b, out);
}

// round 3
// speedup vs baseline: 1.2744x; 1.2744x over previous
#include <cuda_runtime.h>
#include <math.h>

// Fused: binarized-conv(3x3,Cin=1,Cout=32,SAME) + global-avg-pool + dense(32->10) + softmax.
// pooling commutes with conv: p[b,co] = conv_b[co] + (1/4096)*sum_k sign(w[k,co])*S[b,k],
// S[b,k] = 9 shifted sums derived from {total, row0, row63, col0, col63, 4 corners}.

#define B_TOTAL 512
#define HW 4096
#define NCO 32
#define NCLS 10

__global__ __launch_bounds__(256, 4)
void fused_bnn_kernel(const float* __restrict__ x,
                      const float* __restrict__ conv_w,   // [9,32]
                      const float* __restrict__ conv_b,   // [32]
                      const float* __restrict__ dense_w,  // [32,10]
                      const float* __restrict__ dense_b,  // [10]
                      float* __restrict__ out)            // [512,10]
{
    __shared__ float warpsum[5][8];
    __shared__ float corn[4];   // x[0,0], x[0,63], x[63,0], x[63,63]

    const int b    = blockIdx.x;
    const int tid  = threadIdx.x;          // 256
    const int lane = tid & 31;
    const int wid  = tid >> 5;
    const float4* img4 = reinterpret_cast<const float4*>(x + (size_t)b * HW);

    // Coalesced: 4 chunks of 256 float4, thread t takes float4 index t+256c.
    // float4 f covers floats [4f,4f+4); row = f>>4; col0 iff (f&15)==0 (x comp);
    // col63 iff (f&15)==15 (w comp). 256 % 16 == 0 so col membership is chunk-invariant.
    float4 v0 = img4[tid];
    float4 v1 = img4[tid + 256];
    float4 v2 = img4[tid + 512];
    float4 v3 = img4[tid + 768];

    float s0 = (v0.x + v0.y) + (v0.z + v0.w);
    float s1 = (v1.x + v1.y) + (v1.z + v1.w);
    float s2 = (v2.x + v2.y) + (v2.z + v2.w);
    float s3 = (v3.x + v3.y) + (v3.z + v3.w);

    float T   = (s0 + s1) + (s2 + s3);
    float R0  = (tid < 16)          ? s0 : 0.0f;   // chunk0, f<16  -> row 0
    float R63 = (tid >= 240)        ? s3 : 0.0f;   // chunk3, f>=1008 -> row 63
    float C0  = ((tid & 15) == 0)   ? (v0.x + v1.x) + (v2.x + v3.x) : 0.0f;
    float C63 = ((tid & 15) == 15)  ? (v0.w + v1.w) + (v2.w + v3.w) : 0.0f;

    // Corners published by their owners (no global reload).
    if (tid == 0)   corn[0] = v0.x;   // x[0,0]
    if (tid == 15)  corn[1] = v0.w;   // x[0,63]
    if (tid == 240) corn[2] = v3.x;   // x[63,0]
    if (tid == 255) corn[3] = v3.w;   // x[63,63]

    #pragma unroll
    for (int off = 16; off > 0; off >>= 1) {
        T   += __shfl_down_sync(0xffffffffu, T,   off);
        R0  += __shfl_down_sync(0xffffffffu, R0,  off);
        R63 += __shfl_down_sync(0xffffffffu, R63, off);
        C0  += __shfl_down_sync(0xffffffffu, C0,  off);
        C63 += __shfl_down_sync(0xffffffffu, C63, off);
    }
    if (lane == 0) {
        warpsum[0][wid] = T;  warpsum[1][wid] = R0;  warpsum[2][wid] = R63;
        warpsum[3][wid] = C0; warpsum[4][wid] = C63;
    }
    __syncthreads();   // the only barrier

    if (wid != 0) return;   // warp 0 finishes the whole epilogue

    // lanes 0..4 reduce their stat across the 8 warps
    float stat = 0.0f;
    if (lane < 5) {
        #pragma unroll
        for (int i = 0; i < 8; i++) stat += warpsum[lane][i];
    }
    const unsigned FULL = 0xffffffffu;
    float t   = __shfl_sync(FULL, stat, 0);
    float r0  = __shfl_sync(FULL, stat, 1);
    float r63 = __shfl_sync(FULL, stat, 2);
    float c0  = __shfl_sync(FULL, stat, 3);
    float c63 = __shfl_sync(FULL, stat, 4);
    float x00 = corn[0], x0e = corn[1], xe0 = corn[2], xee = corn[3];

    // 9 shifted sums (every lane computes; cheap ALU)
    float S[9];
    S[0] = t - r63 - c63 + xee;  S[1] = t - r63;  S[2] = t - r63 - c0 + xe0;
    S[3] = t - c63;              S[4] = t;        S[5] = t - c0;
    S[6] = t - r0  - c63 + x0e;  S[7] = t - r0;   S[8] = t - r0  - c0 + x00;

    // p[lane] = conv_b + (1/4096) * sum_k sign(conv_w[k,lane]) * S[k]
    float acc = 0.0f;
    #pragma unroll
    for (int k = 0; k < 9; k++) {
        float w = conv_w[k * NCO + lane];
        acc += (w >= 0.0f) ? S[k] : -S[k];
    }
    float p = conv_b[lane] + acc * (1.0f / (float)HW);

    // logits via warp broadcast of p; lanes 0..9 accumulate
    float logit = (lane < NCLS) ? dense_b[lane] : 0.0f;
    #pragma unroll
    for (int co = 0; co < NCO; co++) {
        float pc = __shfl_sync(FULL, p, co);
        if (lane < NCLS) logit += pc * dense_w[co * NCLS + lane];
    }

    // softmax across lanes 0..9 (butterfly over full warp, neutral fill)
    float m = (lane < NCLS) ? logit : -INFINITY;
    #pragma unroll
    for (int off = 16; off > 0; off >>= 1)
        m = fmaxf(m, __shfl_xor_sync(FULL, m, off));
    float e = (lane < NCLS) ? expf(logit - m) : 0.0f;
    float d = e;
    #pragma unroll
    for (int off = 16; off > 0; off >>= 1)
        d += __shfl_xor_sync(FULL, d, off);

    if (lane < NCLS) out[b * NCLS + lane] = e / d;
}

extern "C" void kernel_launch(void* const* d_in, const int* in_sizes, int n_in,
                              void* d_out, int out_size) {
    const float* x       = (const float*)d_in[0];
    const float* conv_w  = (const float*)d_in[1];
    const float* conv_b  = (const float*)d_in[2];
    const float* dense_w = (const float*)d_in[3];
    const float* dense_b = (const float*)d_in[4];
    float* out = (float*)d_out;
    (void)in_sizes; (void)n_in; (void)out_size;

    fused_bnn_kernel<<<B_TOTAL, 256>>>(x, conv_w, conv_b, dense_w, dense_b, out);
}